// round 2
// baseline (speedup 1.0000x reference)
#include <cuda_runtime.h>

#define FH 45
#define FW 80
#define CC 64
#define NANCH 2784
#define BATCH 16
#define NO 75      // computed outputs: 2 cls + 73 reg
#define OPAD 80
#define OUTC 77
#define CHUNK 256
#define NCHUNK 11  // ceil(2784/256)

// ---- scratch (device globals; no allocations) ----
__device__ __align__(16) float g_Wc[FH * CC * OPAD];   // [y][ci][o]
__device__ float g_bias[FH * OPAD];                    // [y][o]
__device__ __align__(16) float g_P[BATCH * FH * FW * NO]; // [b][y][x][o] 17.3MB
__device__ int   g_xiT[FH * NANCH];                    // [y][n]: cut x, or -1
__device__ int   g_mode;                               // 1 = mask bytes, 0 = int32

// ---------------------------------------------------------------------------
// Detect invalid_mask storage: if stored as packed bytes, some word > 1.
// ---------------------------------------------------------------------------
__global__ void k_detect(const unsigned* __restrict__ inv_words) {
    __shared__ int s;
    if (threadIdx.x == 0) s = 0;
    __syncthreads();
    int bad = 0;
    const int nInt = (NANCH * FH) / 4;
    for (int i = threadIdx.x; i < nInt; i += blockDim.x)
        if (inv_words[i] > 1u) bad = 1;
    if (bad) atomicOr(&s, 1);
    __syncthreads();
    if (threadIdx.x == 0) g_mode = s;
}

// Build transposed index table: xiT[y][n] = invalid ? -1 : cut_xs[n][y]
__global__ void k_expand(const void* __restrict__ invp,
                         const int* __restrict__ cut_xs) {
    int i = blockIdx.x * blockDim.x + threadIdx.x;   // i = n*FH + y
    if (i >= NANCH * FH) return;
    int n = i / FH, y = i % FH;
    int inv;
    if (g_mode) inv = ((const unsigned char*)invp)[i];
    else        inv = ((const int*)invp)[i];
    g_xiT[y * NANCH + n] = inv ? -1 : cut_xs[i];
}

// ---------------------------------------------------------------------------
// Wc[y,ci,o] = sum_c conv_w[c,ci] * W[c*45+y, o];  bias[y,o] = sum_c conv_b[c]*W
// ---------------------------------------------------------------------------
__global__ void k_weights(const float* __restrict__ conv_w,
                          const float* __restrict__ conv_b,
                          const float* __restrict__ cls_w,
                          const float* __restrict__ reg_w) {
    int t = blockIdx.x * blockDim.x + threadIdx.x;
    if (t >= FH * CC * OPAD) return;
    int o  = t % OPAD;
    int ci = (t / OPAD) % CC;
    int y  = t / (OPAD * CC);
    float acc = 0.f, bacc = 0.f;
    if (o < NO) {
        #pragma unroll 4
        for (int c = 0; c < CC; c++) {
            int k = c * FH + y;
            float w = (o < 2) ? cls_w[k * 2 + o] : reg_w[k * 73 + (o - 2)];
            acc  += conv_w[c * CC + ci] * w;
            bacc += conv_b[c] * w;
        }
    }
    g_Wc[t] = acc;
    if (ci == 0) g_bias[y * OPAD + o] = bacc;
}

// ---------------------------------------------------------------------------
// P[b,y,x,o] = sum_ci x[b,ci,y,x] * Wc[y,ci,o] + bias[y,o]
// ---------------------------------------------------------------------------
__global__ void __launch_bounds__(256) k_feat(const float* __restrict__ x) {
    __shared__ float xs_s[CC][FW];
    __shared__ float wc_s[CC][OPAD];
    __shared__ float b_s[OPAD];
    int b = blockIdx.x / FH;
    int y = blockIdx.x % FH;
    int tid = threadIdx.x;

    for (int idx = tid; idx < CC * FW; idx += 256) {
        int ci = idx / FW, xc = idx % FW;
        xs_s[ci][xc] = x[((b * CC + ci) * FH + y) * FW + xc];
    }
    for (int idx = tid; idx < CC * OPAD; idx += 256)
        wc_s[idx / OPAD][idx % OPAD] = g_Wc[y * CC * OPAD + idx];
    if (tid < OPAD) b_s[tid] = g_bias[y * OPAD + tid];
    __syncthreads();

    int og = tid >> 4;
    int xg = tid & 15;
    float acc[5][5];
    #pragma unroll
    for (int j = 0; j < 5; j++) {
        float bb = b_s[og * 5 + j];
        #pragma unroll
        for (int i = 0; i < 5; i++) acc[j][i] = bb;
    }

    #pragma unroll 4
    for (int ci = 0; ci < CC; ci++) {
        float xv[5], wv[5];
        #pragma unroll
        for (int i = 0; i < 5; i++) xv[i] = xs_s[ci][xg * 5 + i];
        #pragma unroll
        for (int j = 0; j < 5; j++) wv[j] = wc_s[ci][og * 5 + j];
        #pragma unroll
        for (int j = 0; j < 5; j++)
            #pragma unroll
            for (int i = 0; i < 5; i++)
                acc[j][i] += wv[j] * xv[i];
    }

    int base = ((b * FH + y) * FW) * NO;
    #pragma unroll
    for (int j = 0; j < 5; j++) {
        int o = og * 5 + j;
        if (o < NO) {
            #pragma unroll
            for (int i = 0; i < 5; i++)
                g_P[base + (xg * 5 + i) * NO + o] = acc[j][i];
        }
    }
}

// ---------------------------------------------------------------------------
// y-major gather: block = (b, 256-anchor chunk). Per y, stage P[b,y] (24KB)
// in smem; each thread accumulates its anchor's row into 75 registers.
// Bias folded into accumulator init; epilogue smem-staged for coalescing.
// ---------------------------------------------------------------------------
__global__ void __launch_bounds__(256, 2) k_gather2(
        const float* __restrict__ anchors,
        const float* __restrict__ cls_b,
        const float* __restrict__ reg_b,
        float* __restrict__ out) {
    __shared__ __align__(16) float s[FW * NO];   // 6000 floats = 24KB
    int b     = blockIdx.x / NCHUNK;
    int chunk = blockIdx.x % NCHUNK;
    int n0 = chunk * CHUNK;
    int t = threadIdx.x;
    int nA = NANCH - n0; if (nA > CHUNK) nA = CHUNK;
    bool active = (t < nA);
    int n = n0 + t;

    float acc[NO];
    acc[0] = cls_b[0]; acc[1] = cls_b[1];
    #pragma unroll
    for (int j = 0; j < 73; j++) acc[2 + j] = reg_b[j];

    const float* Pb = g_P + (size_t)b * (FH * FW * NO);
    const int NF4 = (FW * NO) / 4;               // 1500
    float4 buf[6];
    {
        const float4* src = (const float4*)Pb;
        #pragma unroll
        for (int k = 0; k < 6; k++) {
            int idx = t + 256 * k;
            if (idx < NF4) buf[k] = src[idx];
        }
    }

    for (int y = 0; y < FH; y++) {
        float4* sd = (float4*)s;
        #pragma unroll
        for (int k = 0; k < 6; k++) {
            int idx = t + 256 * k;
            if (idx < NF4) sd[idx] = buf[k];
        }
        int xv = active ? g_xiT[y * NANCH + n] : -1;
        __syncthreads();
        if (y + 1 < FH) {                         // prefetch next tile
            const float4* src = (const float4*)(Pb + (y + 1) * FW * NO);
            #pragma unroll
            for (int k = 0; k < 6; k++) {
                int idx = t + 256 * k;
                if (idx < NF4) buf[k] = src[idx];
            }
        }
        if (xv >= 0) {
            const float* r = s + xv * NO;        // stride 75: conflict-free
            #pragma unroll
            for (int o = 0; o < NO; o++) acc[o] += r[o];
        }
        __syncthreads();
    }

    // epilogue: 64-anchor rounds, coalesced anchors load + coalesced store
    for (int a0 = 0; a0 < nA; a0 += 64) {
        int rows = nA - a0; if (rows > 64) rows = 64;
        int tot = rows * OUTC;
        const float* ap = anchors + (size_t)(n0 + a0) * OUTC;
        for (int idx = t; idx < tot; idx += 256) s[idx] = ap[idx];
        __syncthreads();
        int r = t - a0;
        if (r >= 0 && r < rows) {
            float* sr = s + r * OUTC;            // stride 77: conflict-free
            sr[0] = acc[0];
            sr[1] = acc[1];                       // sr[2],sr[3] stay = anchors p24
            #pragma unroll
            for (int j = 0; j < 73; j++) sr[4 + j] += acc[2 + j];
        }
        __syncthreads();
        float* op = out + (size_t)(b * NANCH + n0 + a0) * OUTC;
        for (int idx = t; idx < tot; idx += 256) op[idx] = s[idx];
        __syncthreads();
    }
}

// ---------------------------------------------------------------------------
extern "C" void kernel_launch(void* const* d_in, const int* in_sizes, int n_in,
                              void* d_out, int out_size) {
    const float* x       = (const float*)d_in[0];
    const float* conv_w  = (const float*)d_in[1];
    const float* conv_b  = (const float*)d_in[2];
    const float* cls_w   = (const float*)d_in[3];
    const float* cls_b   = (const float*)d_in[4];
    const float* reg_w   = (const float*)d_in[5];
    const float* reg_b   = (const float*)d_in[6];
    const float* anchors = (const float*)d_in[7];
    const int*   cut_xs  = (const int*)d_in[8];
    const void*  inv     = d_in[9];
    float* out = (float*)d_out;

    k_detect<<<1, 256>>>((const unsigned*)inv);
    k_expand<<<(NANCH * FH + 255) / 256, 256>>>(inv, cut_xs);
    k_weights<<<(FH * CC * OPAD + 255) / 256, 256>>>(conv_w, conv_b, cls_w, reg_w);
    k_feat<<<BATCH * FH, 256>>>(x);
    k_gather2<<<BATCH * NCHUNK, 256>>>(anchors, cls_b, reg_b, out);
}

// round 5
// speedup vs baseline: 1.1462x; 1.1462x over previous
#include <cuda_runtime.h>

#define FH 45
#define FW 80
#define CC 64
#define NANCH 2784
#define BATCH 16
#define NO 75      // computed outputs: 2 cls + 73 reg
#define OPAD 80
#define OUTC 77
#define GCH 160    // gather anchors per block
#define GNCH 18    // ceil(2784/160)

// ---- scratch (device globals; no allocations) ----
__device__ __align__(16) float g_Wc[FH * CC * OPAD];      // [y][ci][o]
__device__ float g_bias[FH * OPAD];                       // [y][o]
__device__ __align__(16) float g_P[BATCH * FH * FW * NO]; // [b][y][x][o] 17.3MB
__device__ int   g_xiT[FH * NANCH];                       // [y][n]: cut x, or -1
__device__ int   g_mode;                                  // 1 = mask bytes, 0 = int32

// ---------------------------------------------------------------------------
__global__ void k_detect(const unsigned* __restrict__ inv_words) {
    __shared__ int s;
    if (threadIdx.x == 0) s = 0;
    __syncthreads();
    int bad = 0;
    const int nInt = (NANCH * FH) / 4;
    for (int i = threadIdx.x; i < nInt; i += blockDim.x)
        if (inv_words[i] > 1u) bad = 1;
    if (bad) atomicOr(&s, 1);
    __syncthreads();
    if (threadIdx.x == 0) g_mode = s;
}

__global__ void k_expand(const void* __restrict__ invp,
                         const int* __restrict__ cut_xs) {
    int i = blockIdx.x * blockDim.x + threadIdx.x;   // i = n*FH + y
    if (i >= NANCH * FH) return;
    int n = i / FH, y = i % FH;
    int inv;
    if (g_mode) inv = ((const unsigned char*)invp)[i];
    else        inv = ((const int*)invp)[i];
    g_xiT[y * NANCH + n] = inv ? -1 : cut_xs[i];
}

// ---------------------------------------------------------------------------
// Wc[y,ci,o] = sum_c conv_w[c,ci]*W[c*45+y,o]; smem-tiled, one block per y.
// ---------------------------------------------------------------------------
__global__ void __launch_bounds__(256) k_weights2(const float* __restrict__ conv_w,
                                                  const float* __restrict__ conv_b,
                                                  const float* __restrict__ cls_w,
                                                  const float* __restrict__ reg_w) {
    __shared__ float w_s[CC * NO];      // [c][o]
    __shared__ float conv_s[CC * CC];   // [c][ci]
    int y = blockIdx.x;
    int tid = threadIdx.x;
    for (int idx = tid; idx < CC * NO; idx += 256) {
        int c = idx / NO, o = idx % NO;
        int k = c * FH + y;
        w_s[idx] = (o < 2) ? cls_w[k * 2 + o] : reg_w[k * 73 + (o - 2)];
    }
    for (int idx = tid; idx < CC * CC; idx += 256) conv_s[idx] = conv_w[idx];
    __syncthreads();
    for (int idx = tid; idx < CC * OPAD; idx += 256) {
        int ci = idx / OPAD, o = idx % OPAD;
        float acc = 0.f;
        if (o < NO) {
            #pragma unroll 8
            for (int c = 0; c < CC; c++) acc += conv_s[c * CC + ci] * w_s[c * NO + o];
        }
        g_Wc[y * CC * OPAD + idx] = acc;
    }
    if (tid < OPAD) {
        float bacc = 0.f;
        if (tid < NO) {
            #pragma unroll 8
            for (int c = 0; c < CC; c++) bacc += conv_b[c] * w_s[c * NO + tid];
        }
        g_bias[y * OPAD + tid] = bacc;
    }
}

// ---------------------------------------------------------------------------
// P[b,y,x,o] = sum_ci x[b,ci,y,x]*Wc[y,ci,o] + bias[y,o]
// Pipelined LDS; smem-staged coalesced float4 stores.
// ---------------------------------------------------------------------------
__global__ void __launch_bounds__(256) k_feat(const float* __restrict__ x) {
    __shared__ __align__(16) float smem[CC * FW + CC * OPAD + OPAD]; // 10320 f
    float* xs_s = smem;            // [64][80]
    float* wc_s = smem + CC * FW;  // [64][80]
    float* b_s  = smem + CC * FW + CC * OPAD;
    int b = blockIdx.x / FH;
    int y = blockIdx.x % FH;
    int tid = threadIdx.x;

    for (int idx = tid; idx < CC * FW; idx += 256) {
        int ci = idx / FW, xc = idx % FW;
        xs_s[idx] = x[((b * CC + ci) * FH + y) * FW + xc];
    }
    {
        const float4* wsrc = (const float4*)(g_Wc + y * CC * OPAD);
        float4* wdst = (float4*)wc_s;
        for (int idx = tid; idx < (CC * OPAD) / 4; idx += 256) wdst[idx] = wsrc[idx];
    }
    if (tid < OPAD) b_s[tid] = g_bias[y * OPAD + tid];
    __syncthreads();

    int og = tid >> 4;
    int xg = tid & 15;
    const float* xp = xs_s + xg * 5;
    const float* wp = wc_s + og * 5;

    float acc[5][5];
    #pragma unroll
    for (int j = 0; j < 5; j++) {
        float bb = b_s[og * 5 + j];
        #pragma unroll
        for (int i = 0; i < 5; i++) acc[j][i] = bb;
    }

    float xv[5], wv[5];
    #pragma unroll
    for (int i = 0; i < 5; i++) { xv[i] = xp[i]; wv[i] = wp[i]; }

    #pragma unroll 4
    for (int ci = 0; ci < CC; ci++) {
        float xn[5], wn[5];
        if (ci + 1 < CC) {
            const float* xq = xp + (ci + 1) * FW;
            const float* wq = wp + (ci + 1) * OPAD;
            #pragma unroll
            for (int i = 0; i < 5; i++) { xn[i] = xq[i]; wn[i] = wq[i]; }
        }
        #pragma unroll
        for (int j = 0; j < 5; j++)
            #pragma unroll
            for (int i = 0; i < 5; i++)
                acc[j][i] += wv[j] * xv[i];
        #pragma unroll
        for (int i = 0; i < 5; i++) { xv[i] = xn[i]; wv[i] = wn[i]; }
    }

    // stage P tile [x*75+o] in smem (overlays xs/wc), then coalesced store
    __syncthreads();
    #pragma unroll
    for (int j = 0; j < 5; j++) {
        int o = og * 5 + j;
        if (o < NO) {
            #pragma unroll
            for (int i = 0; i < 5; i++)
                smem[(xg * 5 + i) * NO + o] = acc[j][i];
        }
    }
    __syncthreads();
    {
        float4* dst = (float4*)(g_P + (size_t)(b * FH + y) * (FW * NO));
        const float4* srcv = (const float4*)smem;
        for (int idx = tid; idx < (FW * NO) / 4; idx += 256) dst[idx] = srcv[idx];
    }
}

// ---------------------------------------------------------------------------
// Gather: block = (b, 160-anchor chunk); 320 threads = 160 anchors x 2 o-halves
// (h warp-pure: warps 0-4 h=0, 5-9 h=1). Per y: stage P[b,y] tile (24KB) in
// smem (reg-double-buffered), accumulate 38/37 outputs per thread.
// ---------------------------------------------------------------------------
__global__ void __launch_bounds__(320) k_gather3(
        const float* __restrict__ anchors,
        const float* __restrict__ cls_b,
        const float* __restrict__ reg_b,
        float* __restrict__ out) {
    __shared__ __align__(16) float s[FW * NO];   // 6000 floats = 24KB
    int b     = blockIdx.x / GNCH;
    int chunk = blockIdx.x % GNCH;
    int n0 = chunk * GCH;
    int nA = NANCH - n0; if (nA > GCH) nA = GCH;
    int t = threadIdx.x;
    int a = t % GCH;          // 0..159
    int h = t / GCH;          // 0 or 1 (warp-pure)
    bool active = (a < nA);
    int n = n0 + a;

    float acc[38];
    if (h == 0) {
        acc[0] = cls_b[0]; acc[1] = cls_b[1];
        #pragma unroll
        for (int j = 0; j < 36; j++) acc[2 + j] = reg_b[j];        // o = 2..37
    } else {
        #pragma unroll
        for (int j = 0; j < 37; j++) acc[j] = reg_b[36 + j];       // o = 38..74
        acc[37] = 0.f;
    }

    const float* Pb = g_P + (size_t)b * (FH * FW * NO);
    const int NF4 = (FW * NO) / 4;               // 1500
    float4 buf[5];
    {
        const float4* src = (const float4*)Pb;
        #pragma unroll
        for (int k = 0; k < 5; k++) {
            int idx = t + 320 * k;
            if (idx < NF4) buf[k] = src[idx];
        }
    }

    for (int y = 0; y < FH; y++) {
        float4* sd = (float4*)s;
        #pragma unroll
        for (int k = 0; k < 5; k++) {
            int idx = t + 320 * k;
            if (idx < NF4) sd[idx] = buf[k];
        }
        int xv = active ? g_xiT[y * NANCH + n] : -1;
        __syncthreads();
        if (y + 1 < FH) {
            const float4* src = (const float4*)(Pb + (size_t)(y + 1) * (FW * NO));
            #pragma unroll
            for (int k = 0; k < 5; k++) {
                int idx = t + 320 * k;
                if (idx < NF4) buf[k] = src[idx];
            }
        }
        if (xv >= 0) {
            const float* r = s + xv * NO;
            if (h == 0) {
                #pragma unroll
                for (int o = 0; o < 38; o++) acc[o] += r[o];
            } else {
                #pragma unroll
                for (int o = 0; o < 37; o++) acc[o] += r[38 + o];
            }
        }
        __syncthreads();
    }

    // epilogue: 64-anchor rounds, coalesced anchors load + coalesced store
    for (int a0 = 0; a0 < nA; a0 += 64) {
        int rows = nA - a0; if (rows > 64) rows = 64;
        int tot = rows * OUTC;
        const float* ap = anchors + (size_t)(n0 + a0) * OUTC;
        for (int idx = t; idx < tot; idx += 320) s[idx] = ap[idx];
        __syncthreads();
        int r = a - a0;
        if (r >= 0 && r < rows) {
            float* sr = s + r * OUTC;
            if (h == 0) {
                sr[0] = acc[0];
                sr[1] = acc[1];
                #pragma unroll
                for (int j = 0; j < 36; j++) sr[4 + j] += acc[2 + j];  // cols 4..39
            } else {
                #pragma unroll
                for (int j = 0; j < 37; j++) sr[40 + j] += acc[j];     // cols 40..76
            }
        }
        __syncthreads();
        float* op = out + (size_t)(b * NANCH + n0 + a0) * OUTC;
        for (int idx = t; idx < tot; idx += 320) op[idx] = s[idx];
        __syncthreads();
    }
}

// ---------------------------------------------------------------------------
extern "C" void kernel_launch(void* const* d_in, const int* in_sizes, int n_in,
                              void* d_out, int out_size) {
    const float* x       = (const float*)d_in[0];
    const float* conv_w  = (const float*)d_in[1];
    const float* conv_b  = (const float*)d_in[2];
    const float* cls_w   = (const float*)d_in[3];
    const float* cls_b   = (const float*)d_in[4];
    const float* reg_w   = (const float*)d_in[5];
    const float* reg_b   = (const float*)d_in[6];
    const float* anchors = (const float*)d_in[7];
    const int*   cut_xs  = (const int*)d_in[8];
    const void*  inv     = d_in[9];
    float* out = (float*)d_out;

    k_detect<<<1, 256>>>((const unsigned*)inv);
    k_expand<<<(NANCH * FH + 255) / 256, 256>>>(inv, cut_xs);
    k_weights2<<<FH, 256>>>(conv_w, conv_b, cls_w, reg_w);
    k_feat<<<BATCH * FH, 256>>>(x);
    k_gather3<<<BATCH * GNCH, 320>>>(anchors, cls_b, reg_b, out);
}